// round 12
// baseline (speedup 1.0000x reference)
#include <cuda_runtime.h>
#include <cuda_fp16.h>
#include <cstdint>
#include <math.h>

#define Hh 128
#define Ww 128
#define Ho 126
#define Wo 126
#define HOWO (126*126)
#define NCH 36              // 9 taps * 4 chunks of 32 channels

// fp16 weights, fragment-interleaved: [ch][g][co][slot u16 x16]
// slot S (u32 granularity, 8 per row): S even -> k{S,S+1}, S odd -> k{S+7,S+8}
__device__ __half g_wt[NCH * 2 * 128 * 16];

__device__ __forceinline__ uint32_t smem_u32(const void* p) {
    uint32_t a;
    asm("{ .reg .u64 t; cvta.to.shared.u64 t, %1; cvt.u32.u64 %0, t; }" : "=r"(a) : "l"(p));
    return a;
}

// ---------------------------------------------------------------------------
// Weight prep: w[o][c][kh][kw] -> fp16, interleaved fragment layout
// ---------------------------------------------------------------------------
__global__ void wt_prep(const float* __restrict__ w) {
    int id = blockIdx.x * blockDim.x + threadIdx.x;
    if (id >= 9 * 128 * 128) return;
    int o = id & 127, c = (id >> 7) & 127, tap = id >> 14;
    int ch = tap * 4 + (c >> 5);
    int g  = (c >> 4) & 1;
    int k  = c & 15;
    int S    = (k < 8) ? (k & ~1) : (((k - 8) & ~1) + 1);
    int half = k & 1;
    float v = w[(o * 128 + c) * 9 + tap];
    g_wt[(((ch * 2 + g) * 128 + o) * 16) + S * 2 + half] = __float2half_rn(v);
}

// ---------------------------------------------------------------------------
// Main kernel: CTA per (ho, n, pix-half). D[pix 64, co 128] fp16 m16n8k16.
// 8 warps: warp tile M32 x N32. 3 CTAs/SM target.
// ---------------------------------------------------------------------------
__global__ void __launch_bounds__(256, 3)
adc_mma(const float* __restrict__ inp, const float* __restrict__ rates,
        const float* __restrict__ bias, float* __restrict__ out)
{
    __shared__ uint32_t sampS[2][2][64][8];    // [buf][g][pix][8 u32]  8KB
    __shared__ uint32_t wS[2][2][128][8];      // [buf][g][co][8 u32]  16KB
    __shared__ float rbuf[64];

    const int t = threadIdx.x, lane = t & 31, wrp = t >> 5;
    const int ho = blockIdx.x, n = blockIdx.y;
    const int px0 = blockIdx.z << 6;           // 0 or 64

    // rate map: bilinear upsample rates[32x32] -> (ho, px0+pix)
    if (t < 64) {
        const float scale = (float)(32.0 / 126.0);
        int wo = px0 + t;
        float sy = fminf(fmaxf(((float)ho + 0.5f) * scale - 0.5f, 0.0f), 31.0f);
        float sx = fminf(fmaxf(((float)wo + 0.5f) * scale - 0.5f, 0.0f), 31.0f);
        float y0f = floorf(sy), x0f = floorf(sx);
        int y0 = (int)y0f, x0 = (int)x0f;
        int y1 = min(y0 + 1, 31), x1 = min(x0 + 1, 31);
        float wy = sy - y0f, wx = sx - x0f;
        rbuf[t] = rates[y0 * 32 + x0] * (1.f - wy) * (1.f - wx)
                + rates[y0 * 32 + x1] * (1.f - wy) * wx
                + rates[y1 * 32 + x0] * wy * (1.f - wx)
                + rates[y1 * 32 + x1] * wy * wx;
    }
    __syncthreads();

    const int pix = t & 63;                    // local pixel
    const int q   = t >> 6;                    // 0..3
    const int gg  = q & 1;                     // k-group for gather
    const int s4  = (q >> 1) << 2;             // slot base: 0 or 4
    const int wo  = px0 + pix;
    const float rate = rbuf[pix];
    const float fvalid = (wo < Wo) ? 1.0f : 0.0f;

    // bilinear coeffs for current tap (register resident, fixed pix per thread)
    float cw0, cw1, cw2, cw3;
    int o0, o1, o2, o3;
    auto calc = [&](int tap) {
        int kh = tap / 3, kw = tap - kh * 3;
        float fy = (float)ho + (float)kh * rate;
        float fx = (float)wo + (float)kw * rate;
        float y0f = floorf(fy), x0f = floorf(fx);
        float wy = fy - y0f, wx = fx - x0f;
        int y0 = (int)y0f, x0 = (int)x0f;
        int y1 = y0 + 1,  x1 = x0 + 1;
        float my0 = (y0 >= 0 && y0 < Hh) ? 1.f : 0.f;
        float my1 = (y1 >= 0 && y1 < Hh) ? 1.f : 0.f;
        float mx0 = (x0 >= 0 && x0 < Ww) ? 1.f : 0.f;
        float mx1 = (x1 >= 0 && x1 < Ww) ? 1.f : 0.f;
        cw0 = (1.f - wy) * (1.f - wx) * my0 * mx0 * fvalid;
        cw1 = (1.f - wy) * wx         * my0 * mx1 * fvalid;
        cw2 = wy * (1.f - wx)         * my1 * mx0 * fvalid;
        cw3 = wy * wx                 * my1 * mx1 * fvalid;
        int y0c = min(max(y0, 0), Hh - 1), y1c = min(max(y1, 0), Hh - 1);
        int x0c = min(max(x0, 0), Ww - 1), x1c = min(max(x1, 0), Ww - 1);
        o0 = y0c * Ww + x0c; o1 = y0c * Ww + x1c;
        o2 = y1c * Ww + x0c; o3 = y1c * Ww + x1c;
    };

    uint32_t ug[4];         // gathered fp16x2 slots s4..s4+3 of group gg
    float4 w0r, w1r;        // weight chunk prefetch
    auto gather = [&](int ch) {
        const int cb = n * 128 + (ch & 3) * 32 + gg * 16;
        const float* pg = inp + ((size_t)cb << 14);
        #pragma unroll
        for (int s = 0; s < 4; s++) {
            int S  = s4 + s;
            int kA = (S & 1) ? (S + 7) : S;
            const float* p = pg + ((size_t)kA << 14);
            float e = cw0 * __ldg(p + o0) + cw1 * __ldg(p + o1)
                    + cw2 * __ldg(p + o2) + cw3 * __ldg(p + o3);
            const float* qq = p + 16384;
            float od = cw0 * __ldg(qq + o0) + cw1 * __ldg(qq + o1)
                     + cw2 * __ldg(qq + o2) + cw3 * __ldg(qq + o3);
            asm("cvt.rn.f16x2.f32 %0, %1, %2;" : "=r"(ug[s]) : "f"(od), "f"(e));
        }
        const float4* ws = (const float4*)g_wt + ch * 512 + t;
        w0r = __ldg(ws);
        w1r = __ldg(ws + 256);
    };

    calc(0);
    gather(0);

    // warp tile: M32 x N32 ; warps = 2 m x 4 n
    const int m0 = (wrp & 1) * 32, n0 = (wrp >> 1) * 32;

    // accumulators init = bias
    float acc[2][4][4];
    #pragma unroll
    for (int ni = 0; ni < 4; ni++) {
        int cb = n0 + ni * 8 + (lane & 3) * 2;
        float b0 = __ldg(bias + cb), b1 = __ldg(bias + cb + 1);
        #pragma unroll
        for (int mi = 0; mi < 2; mi++) {
            acc[mi][ni][0] = b0; acc[mi][ni][1] = b1;
            acc[mi][ni][2] = b0; acc[mi][ni][3] = b1;
        }
    }

    const uint32_t sa = smem_u32(sampS), wa = smem_u32(wS);
    const uint32_t xorv = (pix & 4) << 2;    // 16B-half XOR swizzle (samp only)
    const uint32_t sts_addr_base = (uint32_t)(gg * 64 + pix) * 32
                                 + (((uint32_t)s4 * 4) ^ xorv);

    for (int ch = 0; ch < NCH; ch++) {
        const int st = ch & 1;
        const uint32_t sbase = sa + st * 4096;
        const uint32_t wbase = wa + st * 8192;

        // ---- STS gathered fp16 samples + weights (from prev gather) ----
        asm volatile("st.shared.v4.b32 [%0], {%1,%2,%3,%4};"
                     :: "r"(sbase + sts_addr_base),
                        "r"(ug[0]), "r"(ug[1]), "r"(ug[2]), "r"(ug[3]));
        {
            float4* wd = (float4*)(wS[st]);
            wd[t] = w0r;
            wd[t + 256] = w1r;
        }
        __syncthreads();   // single barrier per chunk: publishes buf[st],
                           // and guards buf[st^1] overwrite next iteration

        // ---- issue next gather (LDGs overlap MMA across warps) ----
        if (ch < NCH - 1) {
            int c1 = ch + 1;
            if ((c1 & 3) == 0) calc(c1 >> 2);
            gather(c1);
        }

        // ---- MMA: 2 k16-groups x (2 m16 x 4 n8) ----
        #pragma unroll
        for (int g = 0; g < 2; g++) {
            const uint32_t ab = sbase + (uint32_t)g * 2048;
            const uint32_t bb = wbase + (uint32_t)g * 4096;
            const uint32_t k8off = (lane & 3) * 8;
            uint32_t A[2][4];
            #pragma unroll
            for (int mi = 0; mi < 2; mi++) {
                int r0 = m0 + mi * 16 + (lane >> 2);
                int r1 = r0 + 8;
                uint32_t ad0 = ab + (uint32_t)r0 * 32 + (k8off ^ ((r0 & 4) << 2));
                uint32_t ad1 = ab + (uint32_t)r1 * 32 + (k8off ^ ((r1 & 4) << 2));
                asm volatile("ld.shared.v2.b32 {%0,%1}, [%2];"
                             : "=r"(A[mi][0]), "=r"(A[mi][2]) : "r"(ad0));
                asm volatile("ld.shared.v2.b32 {%0,%1}, [%2];"
                             : "=r"(A[mi][1]), "=r"(A[mi][3]) : "r"(ad1));
            }
            #pragma unroll
            for (int ni = 0; ni < 4; ni++) {
                int co = n0 + ni * 8 + (lane >> 2);
                uint32_t bd = bb + (uint32_t)co * 32 + k8off;
                uint32_t B0, B1;
                asm volatile("ld.shared.v2.b32 {%0,%1}, [%2];"
                             : "=r"(B0), "=r"(B1) : "r"(bd));
                #pragma unroll
                for (int mi = 0; mi < 2; mi++) {
                    asm volatile(
                        "mma.sync.aligned.m16n8k16.row.col.f32.f16.f16.f32 "
                        "{%0,%1,%2,%3}, {%4,%5,%6,%7}, {%8,%9}, {%0,%1,%2,%3};"
                        : "+f"(acc[mi][ni][0]), "+f"(acc[mi][ni][1]),
                          "+f"(acc[mi][ni][2]), "+f"(acc[mi][ni][3])
                        : "r"(A[mi][0]), "r"(A[mi][1]), "r"(A[mi][2]), "r"(A[mi][3]),
                          "r"(B0), "r"(B1));
                }
            }
        }
    }

    // ---- epilogue: scatter C frags to out[n][co][ho][wo] ----
    #pragma unroll
    for (int mi = 0; mi < 2; mi++) {
        int r0 = m0 + mi * 16 + (lane >> 2);
        int r1 = r0 + 8;
        int w0g = px0 + r0, w1g = px0 + r1;
        #pragma unroll
        for (int ni = 0; ni < 4; ni++) {
            int co = n0 + ni * 8 + (lane & 3) * 2;
            float* p0 = out + (size_t)(n * 128 + co) * HOWO + ho * Wo;
            float* p1 = p0 + HOWO;
            if (w0g < Wo) { p0[w0g] = acc[mi][ni][0]; p1[w0g] = acc[mi][ni][1]; }
            if (w1g < Wo) { p0[w1g] = acc[mi][ni][2]; p1[w1g] = acc[mi][ni][3]; }
        }
    }
}

// ---------------------------------------------------------------------------
extern "C" void kernel_launch(void* const* d_in, const int* in_sizes, int n_in,
                              void* d_out, int out_size) {
    const float* inp   = (const float*)d_in[0];  // [8,128,128,128]
    const float* wgt   = (const float*)d_in[1];  // [128,128,3,3]
    const float* rates = (const float*)d_in[2];  // [1,1,32,32]
    const float* bias  = (const float*)d_in[3];  // [128]
    float* out = (float*)d_out;

    wt_prep<<<(9 * 128 * 128 + 255) / 256, 256>>>(wgt);

    dim3 grid(Ho, 8, 2);   // (126, 8, 2) = 2016 CTAs
    adc_mma<<<grid, 256>>>(inp, rates, bias, out);
}

// round 13
// speedup vs baseline: 1.1214x; 1.1214x over previous
#include <cuda_runtime.h>
#include <cuda_fp16.h>
#include <cstdint>
#include <math.h>

#define Hh 128
#define Ww 128
#define Ho 126
#define Wo 126
#define HOWO (126*126)
#define NCH 36              // 9 taps * 4 chunks of 32 channels

// B-fragment-ordered fp16 weights:
// [ch(36)][ncol(4)][ni(4)][lane(32)][4 u32] ; each u32 slot = {g0r0,g0r1,g1r0,g1r1}
// lane = n_in_8*4 + j (j=k-pair), u32 halves = fp16 {k=2j+8r .. }
__device__ __half g_wt[NCH * 4 * 4 * 32 * 8];

__device__ __forceinline__ uint32_t smem_u32(const void* p) {
    uint32_t a;
    asm("{ .reg .u64 t; cvta.to.shared.u64 t, %1; cvt.u32.u64 %0, t; }" : "=r"(a) : "l"(p));
    return a;
}

// ---------------------------------------------------------------------------
// Weight prep: w[o][c][kh][kw] -> fp16, direct B-fragment layout
// ---------------------------------------------------------------------------
__global__ void wt_prep(const float* __restrict__ w) {
    int id = blockIdx.x * blockDim.x + threadIdx.x;
    if (id >= 9 * 128 * 128) return;
    int o = id & 127, c = (id >> 7) & 127, tap = id >> 14;
    int ch = tap * 4 + (c >> 5);
    int k  = c & 31;
    int g  = k >> 4;
    int kk = k & 15;
    int r  = (kk >= 8) ? 1 : 0;
    int kk8 = kk & 7;
    int j = kk8 >> 1, half = kk8 & 1;
    int ncol = o >> 5;
    int oo = o & 31;
    int ni = oo >> 3, nn = oo & 7;
    int lane = nn * 4 + j;
    int u32idx = (((ch * 4 + ncol) * 4 + ni) * 32 + lane) * 4 + g * 2 + r;
    g_wt[u32idx * 2 + half] = __float2half_rn(w[(o * 128 + c) * 9 + tap]);
}

// ---------------------------------------------------------------------------
// Main kernel: CTA per (ho, n). D[pix 128, co 128] fp16 m16n8k16.
// 8 warps = 2 m-rows x 4 n-cols, warp tile M64 x N32. B direct from gmem.
// ---------------------------------------------------------------------------
__global__ void __launch_bounds__(256, 2)
adc_mma(const float* __restrict__ inp, const float* __restrict__ rates,
        const float* __restrict__ bias, float* __restrict__ out)
{
    __shared__ uint32_t sampS[2][2][128][8];   // [buf][g][pix][8 u32]  16KB
    __shared__ float rbuf[128];

    const int t = threadIdx.x, lane = t & 31, wrp = t >> 5;
    const int ho = blockIdx.x, n = blockIdx.y;

    // rate map: bilinear upsample rates[32x32] -> (ho, pix)
    if (t < 128) {
        const float scale = (float)(32.0 / 126.0);
        float sy = fminf(fmaxf(((float)ho + 0.5f) * scale - 0.5f, 0.0f), 31.0f);
        float sx = fminf(fmaxf(((float)t  + 0.5f) * scale - 0.5f, 0.0f), 31.0f);
        float y0f = floorf(sy), x0f = floorf(sx);
        int y0 = (int)y0f, x0 = (int)x0f;
        int y1 = min(y0 + 1, 31), x1 = min(x0 + 1, 31);
        float wy = sy - y0f, wx = sx - x0f;
        rbuf[t] = rates[y0 * 32 + x0] * (1.f - wy) * (1.f - wx)
                + rates[y0 * 32 + x1] * (1.f - wy) * wx
                + rates[y1 * 32 + x0] * wy * (1.f - wx)
                + rates[y1 * 32 + x1] * wy * wx;
    }
    __syncthreads();

    const int pix = t & 127, kg = t >> 7;
    const float rate = rbuf[pix];
    const float fvalid = (pix < Wo) ? 1.0f : 0.0f;

    // bilinear coeffs for current tap (register resident, fixed pix per thread)
    float cw0, cw1, cw2, cw3;
    int o0, o1, o2, o3;
    auto calc = [&](int tap) {
        int kh = tap / 3, kw = tap - kh * 3;
        float fy = (float)ho  + (float)kh * rate;
        float fx = (float)pix + (float)kw * rate;
        float y0f = floorf(fy), x0f = floorf(fx);
        float wy = fy - y0f, wx = fx - x0f;
        int y0 = (int)y0f, x0 = (int)x0f;
        int y1 = y0 + 1,  x1 = x0 + 1;
        float my0 = (y0 >= 0 && y0 < Hh) ? 1.f : 0.f;
        float my1 = (y1 >= 0 && y1 < Hh) ? 1.f : 0.f;
        float mx0 = (x0 >= 0 && x0 < Ww) ? 1.f : 0.f;
        float mx1 = (x1 >= 0 && x1 < Ww) ? 1.f : 0.f;
        cw0 = (1.f - wy) * (1.f - wx) * my0 * mx0 * fvalid;
        cw1 = (1.f - wy) * wx         * my0 * mx1 * fvalid;
        cw2 = wy * (1.f - wx)         * my1 * mx0 * fvalid;
        cw3 = wy * wx                 * my1 * mx1 * fvalid;
        int y0c = min(max(y0, 0), Hh - 1), y1c = min(max(y1, 0), Hh - 1);
        int x0c = min(max(x0, 0), Ww - 1), x1c = min(max(x1, 0), Ww - 1);
        o0 = y0c * Ww + x0c; o1 = y0c * Ww + x1c;
        o2 = y1c * Ww + x0c; o3 = y1c * Ww + x1c;
    };

    uint32_t ug[2][4];      // gathered fp16x2 slots, per g group
    auto gather = [&](int ch) {
        const int cb = n * 128 + (ch & 3) * 32;
        #pragma unroll
        for (int g = 0; g < 2; g++) {
            const float* pg = inp + ((size_t)(cb + g * 16) << 14);
            #pragma unroll
            for (int s = 0; s < 4; s++) {
                int S  = 4 * kg + s;
                int kA = (S & 1) ? (S + 7) : S;
                const float* p = pg + ((size_t)kA << 14);
                float e = cw0 * __ldg(p + o0) + cw1 * __ldg(p + o1)
                        + cw2 * __ldg(p + o2) + cw3 * __ldg(p + o3);
                const float* q = p + 16384;
                float od = cw0 * __ldg(q + o0) + cw1 * __ldg(q + o1)
                         + cw2 * __ldg(q + o2) + cw3 * __ldg(q + o3);
                asm("cvt.rn.f16x2.f32 %0, %1, %2;" : "=r"(ug[g][s]) : "f"(od), "f"(e));
            }
        }
    };

    calc(0);
    gather(0);

    // warp tile: M64 x N32 ; warps = 2 m-rows x 4 n-cols
    const int m0   = (wrp & 1) * 64;
    const int ncol = wrp >> 1;
    const int n0   = ncol * 32;

    // accumulators init = bias
    float acc[4][4][4];
    #pragma unroll
    for (int ni = 0; ni < 4; ni++) {
        int cb = n0 + ni * 8 + (lane & 3) * 2;
        float b0 = __ldg(bias + cb), b1 = __ldg(bias + cb + 1);
        #pragma unroll
        for (int mi = 0; mi < 4; mi++) {
            acc[mi][ni][0] = b0; acc[mi][ni][1] = b1;
            acc[mi][ni][2] = b0; acc[mi][ni][3] = b1;
        }
    }

    const uint32_t sa = smem_u32(sampS);
    const uint32_t xorv = (pix & 4) << 2;    // 16B-half XOR swizzle
    // B fragment gmem base for this warp (per-lane)
    const uint4* gb = (const uint4*)g_wt + (size_t)ncol * 128 + lane;

    for (int ch = 0; ch < NCH; ch++) {
        const int st = ch & 1;
        const uint32_t sbase = sa + st * 8192;

        // ---- STS gathered fp16 samples (from prev gather) ----
        #pragma unroll
        for (int g = 0; g < 2; g++) {
            uint32_t a1 = sbase + (uint32_t)(g * 128 + pix) * 32
                        + ((uint32_t)(kg * 16) ^ xorv);
            asm volatile("st.shared.v4.b32 [%0], {%1,%2,%3,%4};"
                         :: "r"(a1), "r"(ug[g][0]), "r"(ug[g][1]),
                            "r"(ug[g][2]), "r"(ug[g][3]));
        }
        __syncthreads();   // publishes buf[st]; guards buf[st^1] overwrite next iter

        // ---- B fragments: direct LDG.128 from fragment-ordered gmem ----
        uint4 br[4];
        {
            const uint4* gp = gb + (size_t)ch * 512;
            #pragma unroll
            for (int nl = 0; nl < 4; nl++)
                br[nl] = __ldg(gp + nl * 32);
        }

        // ---- issue next gather (LDGs overlap MMA across warps) ----
        if (ch < NCH - 1) {
            int c1 = ch + 1;
            if ((c1 & 3) == 0) calc(c1 >> 2);
            gather(c1);
        }

        // ---- MMA: 2 k16-groups x (4 m16 x 4 n8) ----
        #pragma unroll
        for (int g = 0; g < 2; g++) {
            const uint32_t ab = sbase + (uint32_t)g * 4096;
            const uint32_t k8off = (lane & 3) * 8;
            uint32_t A[4][4];
            #pragma unroll
            for (int mi = 0; mi < 4; mi++) {
                int r0 = m0 + mi * 16 + (lane >> 2);
                int r1 = r0 + 8;
                uint32_t ad0 = ab + (uint32_t)r0 * 32 + (k8off ^ ((r0 & 4) << 2));
                uint32_t ad1 = ab + (uint32_t)r1 * 32 + (k8off ^ ((r1 & 4) << 2));
                asm volatile("ld.shared.v2.b32 {%0,%1}, [%2];"
                             : "=r"(A[mi][0]), "=r"(A[mi][2]) : "r"(ad0));
                asm volatile("ld.shared.v2.b32 {%0,%1}, [%2];"
                             : "=r"(A[mi][1]), "=r"(A[mi][3]) : "r"(ad1));
            }
            #pragma unroll
            for (int ni = 0; ni < 4; ni++) {
                uint32_t B0 = (g == 0) ? br[ni].x : br[ni].z;
                uint32_t B1 = (g == 0) ? br[ni].y : br[ni].w;
                #pragma unroll
                for (int mi = 0; mi < 4; mi++) {
                    asm volatile(
                        "mma.sync.aligned.m16n8k16.row.col.f32.f16.f16.f32 "
                        "{%0,%1,%2,%3}, {%4,%5,%6,%7}, {%8,%9}, {%0,%1,%2,%3};"
                        : "+f"(acc[mi][ni][0]), "+f"(acc[mi][ni][1]),
                          "+f"(acc[mi][ni][2]), "+f"(acc[mi][ni][3])
                        : "r"(A[mi][0]), "r"(A[mi][1]), "r"(A[mi][2]), "r"(A[mi][3]),
                          "r"(B0), "r"(B1));
                }
            }
        }
    }

    // ---- epilogue: scatter C frags to out[n][co][ho][wo] ----
    #pragma unroll
    for (int mi = 0; mi < 4; mi++) {
        int r0 = m0 + mi * 16 + (lane >> 2);
        int r1 = r0 + 8;
        #pragma unroll
        for (int ni = 0; ni < 4; ni++) {
            int co = n0 + ni * 8 + (lane & 3) * 2;
            float* p0 = out + (size_t)(n * 128 + co) * HOWO + ho * Wo;
            float* p1 = p0 + HOWO;
            if (r0 < Wo) { p0[r0] = acc[mi][ni][0]; p1[r0] = acc[mi][ni][1]; }
            if (r1 < Wo) { p0[r1] = acc[mi][ni][2]; p1[r1] = acc[mi][ni][3]; }
        }
    }
}

// ---------------------------------------------------------------------------
extern "C" void kernel_launch(void* const* d_in, const int* in_sizes, int n_in,
                              void* d_out, int out_size) {
    const float* inp   = (const float*)d_in[0];  // [8,128,128,128]
    const float* wgt   = (const float*)d_in[1];  // [128,128,3,3]
    const float* rates = (const float*)d_in[2];  // [1,1,32,32]
    const float* bias  = (const float*)d_in[3];  // [128]
    float* out = (float*)d_out;

    wt_prep<<<(9 * 128 * 128 + 255) / 256, 256>>>(wgt);

    dim3 grid(Ho, 8);   // (126, 8) = 1008 CTAs
    adc_mma<<<grid, 256>>>(inp, rates, bias, out);
}